// round 1
// baseline (speedup 1.0000x reference)
#include <cuda_runtime.h>

// Problem constants
#define BT    4096          // B*T rows
#define TT    1024
#define BB    4
#define MM    128           // n_mels
#define FF    1025          // n_stft
#define FP    1088          // padded F = 17*64
#define NITER 20
#define LRc   0.3f
#define MOMc  0.9f
#define INVc  (2.0f / 4096.0f)

#define ROWS_PER_CTA 32
#define NCTA (BT / ROWS_PER_CTA)   // 128
#define NTHR 256

// Scratch (allowed: static __device__ globals)
__device__ float g_buf[(size_t)BT * FP];   // momentum buffer, zero-padded F
__device__ float g_fbP[FP * MM];           // fb zero-padded to FP rows
__device__ float g_fbT[MM * FP];           // transposed fb, zero-padded

// ---------------- prep kernels ----------------
__global__ void prep_fb_kernel(const float* __restrict__ fb) {
    int idx = blockIdx.x * blockDim.x + threadIdx.x;
    if (idx >= FP * MM) return;
    int f = idx / MM;
    int m = idx - f * MM;
    float v = (f < FF) ? fb[f * MM + m] : 0.0f;
    g_fbP[idx] = v;
    g_fbT[m * FP + f] = v;
}

__global__ void zero_buf_kernel() {
    size_t idx = (size_t)blockIdx.x * blockDim.x + threadIdx.x;
    if (idx < (size_t)BT * FP) g_buf[idx] = 0.0f;
}

// ---------------- main persistent kernel ----------------
// CTA owns 32 consecutive bt-rows for all 20 iterations.
// SMEM: spec[32][FP] fp32 (139264 B) + diff[32][MM] (16384 B) + mel[32][MM] (16384 B) = 172032 B
__global__ __launch_bounds__(NTHR, 1)
void invmel_kernel(const float* __restrict__ melspec,
                   const float* __restrict__ spec_init,
                   float* __restrict__ out) {
    extern __shared__ float sm[];
    float* s_spec = sm;                        // [32][FP]
    float* s_diff = sm + ROWS_PER_CTA * FP;    // [32][MM]
    float* s_mel  = s_diff + ROWS_PER_CTA * MM;

    const int tid  = threadIdx.x;
    const int row0 = blockIdx.x * ROWS_PER_CTA;      // base bt index
    const int b    = row0 / TT;
    const int t0   = row0 - b * TT;                  // 32 consecutive t in same b

    // Load spec tile (coalesced over f), pad cols [FF,FP) with 0
    for (int i = tid; i < ROWS_PER_CTA * FP; i += NTHR) {
        int r = i / FP;
        int f = i - r * FP;
        s_spec[i] = (f < FF) ? spec_init[(size_t)(row0 + r) * FF + f] : 0.0f;
    }
    // Load mel tile: s_mel[r][m] = melspec[b][m][t0+r]  (coalesced over t)
    for (int i = tid; i < ROWS_PER_CTA * MM; i += NTHR) {
        int m = i >> 5;        // 0..127
        int r = i & 31;        // 0..31
        s_mel[r * MM + m] = melspec[((size_t)b * MM + m) * TT + t0 + r];
    }
    __syncthreads();

    // GEMM1 roles: 32 mel-groups (4 mels each) x 8 row-groups (4 rows each)
    const int mq = tid & 31;   // mel base = 4*mq
    const int rq = tid >> 5;   // rows 4*rq .. 4*rq+3
    // GEMM2 roles: 64 f-lanes x 4 row-groups (8 rows each)
    const int ft  = tid & 63;
    const int rq2 = tid >> 6;  // rows 8*rq2 .. 8*rq2+7

    for (int it = 0; it < NITER; ++it) {
        // ---------- GEMM1: diff = mel - spec @ fb ----------
        float acc[4][4];
        #pragma unroll
        for (int i = 0; i < 4; ++i)
            #pragma unroll
            for (int j = 0; j < 4; ++j) acc[i][j] = 0.0f;

        const float4* __restrict__ fbp = reinterpret_cast<const float4*>(g_fbP) + mq;
        #pragma unroll 4
        for (int f = 0; f < FP; ++f) {
            const float4 w = fbp[f * (MM / 4)];
            #pragma unroll
            for (int i = 0; i < 4; ++i) {
                const float sv = s_spec[(4 * rq + i) * FP + f];
                acc[i][0] = fmaf(sv, w.x, acc[i][0]);
                acc[i][1] = fmaf(sv, w.y, acc[i][1]);
                acc[i][2] = fmaf(sv, w.z, acc[i][2]);
                acc[i][3] = fmaf(sv, w.w, acc[i][3]);
            }
        }
        #pragma unroll
        for (int i = 0; i < 4; ++i) {
            const int row = 4 * rq + i;
            float4 mv = *reinterpret_cast<const float4*>(s_mel + row * MM + 4 * mq);
            float4 dv;
            dv.x = mv.x - acc[i][0];
            dv.y = mv.y - acc[i][1];
            dv.z = mv.z - acc[i][2];
            dv.w = mv.w - acc[i][3];
            *reinterpret_cast<float4*>(s_diff + row * MM + 4 * mq) = dv;
        }
        __syncthreads();

        // ---------- GEMM2: grad = -inv * diff @ fbT ; momentum update ----------
        #pragma unroll 1
        for (int p = 0; p < 4; ++p) {
            float a[4][8];
            #pragma unroll
            for (int fj = 0; fj < 4; ++fj)
                #pragma unroll
                for (int r = 0; r < 8; ++r) a[fj][r] = 0.0f;

            const float* __restrict__ fbt = g_fbT + 256 * p + ft;
            #pragma unroll 2
            for (int m = 0; m < MM; ++m) {
                const float w0 = fbt[m * FP];
                const float w1 = fbt[m * FP + 64];
                const float w2 = fbt[m * FP + 128];
                const float w3 = fbt[m * FP + 192];
                #pragma unroll
                for (int r = 0; r < 8; ++r) {
                    const float dvv = s_diff[(8 * rq2 + r) * MM + m];
                    a[0][r] = fmaf(w0, dvv, a[0][r]);
                    a[1][r] = fmaf(w1, dvv, a[1][r]);
                    a[2][r] = fmaf(w2, dvv, a[2][r]);
                    a[3][r] = fmaf(w3, dvv, a[3][r]);
                }
            }
            #pragma unroll
            for (int fj = 0; fj < 4; ++fj) {
                const int f = 256 * p + 64 * fj + ft;
                #pragma unroll
                for (int r = 0; r < 8; ++r) {
                    const int row = 8 * rq2 + r;
                    const size_t gi = (size_t)(row0 + row) * FP + f;
                    const float g  = -INVc * a[fj][r];
                    const float bv = MOMc * g_buf[gi] + g;
                    g_buf[gi] = bv;
                    const float sp = s_spec[row * FP + f] - LRc * bv;
                    s_spec[row * FP + f] = sp > 0.0f ? sp : 0.0f;
                }
            }
        }
        // tail f-block: f = 1024 + ft  (covers 1024..1087; f>=1025 is zero-preserving)
        {
            float a[8];
            #pragma unroll
            for (int r = 0; r < 8; ++r) a[r] = 0.0f;
            const float* __restrict__ fbt = g_fbT + 1024 + ft;
            #pragma unroll 2
            for (int m = 0; m < MM; ++m) {
                const float w = fbt[m * FP];
                #pragma unroll
                for (int r = 0; r < 8; ++r)
                    a[r] = fmaf(w, s_diff[(8 * rq2 + r) * MM + m], a[r]);
            }
            const int f = 1024 + ft;
            #pragma unroll
            for (int r = 0; r < 8; ++r) {
                const int row = 8 * rq2 + r;
                const size_t gi = (size_t)(row0 + row) * FP + f;
                const float g  = -INVc * a[r];
                const float bv = MOMc * g_buf[gi] + g;
                g_buf[gi] = bv;
                const float sp = s_spec[row * FP + f] - LRc * bv;
                s_spec[row * FP + f] = sp > 0.0f ? sp : 0.0f;
            }
        }
        __syncthreads();
    }

    // ---------- epilogue: out[b][f][t0+r] = spec[r][f] ----------
    for (int f = tid; f < FF; f += NTHR) {
        float* op = out + ((size_t)b * FF + f) * TT + t0;
        #pragma unroll 4
        for (int r = 0; r < ROWS_PER_CTA; ++r)
            op[r] = s_spec[r * FP + f];
    }
}

// ---------------- launch ----------------
extern "C" void kernel_launch(void* const* d_in, const int* in_sizes, int n_in,
                              void* d_out, int out_size) {
    const float* melspec   = (const float*)d_in[0];  // (4,128,1024)
    const float* spec_init = (const float*)d_in[1];  // (4,1024,1025)
    const float* fb        = (const float*)d_in[2];  // (1025,128)
    float* out             = (float*)d_out;          // (4,1025,1024)

    const int smem_bytes = (ROWS_PER_CTA * FP + 2 * ROWS_PER_CTA * MM) * sizeof(float); // 172032
    cudaFuncSetAttribute(invmel_kernel, cudaFuncAttributeMaxDynamicSharedMemorySize, smem_bytes);

    prep_fb_kernel<<<(FP * MM + 255) / 256, 256>>>(fb);
    {
        size_t n = (size_t)BT * FP;
        zero_buf_kernel<<<(unsigned)((n + 255) / 256), 256>>>();
    }
    invmel_kernel<<<NCTA, NTHR, smem_bytes>>>(melspec, spec_init, out);
}

// round 3
// speedup vs baseline: 9.3714x; 9.3714x over previous
#include <cuda_runtime.h>

// ---------------- problem constants ----------------
#define MM    128            // n_mels
#define FF    1025           // n_stft
#define FPc   1088           // padded F = 16*68
#define SSTR  1096           // spec SMEM row stride (floats): 1096 % 32 == 8
#define DSTR  133            // mel/diff SMEM row stride
#define TT    1024
#define NITER 20
#define LRc   0.3f
#define MOMc  0.9f
#define INVc  (2.0f / 4096.0f)

#define ROWS  32             // rows per CTA
#define NTHR  512
#define NCTA  128            // 4096 / 32 — single wave on 148 SMs
#define CHNK  68             // f per thread (FPc/16)
#define CSRK  64             // padded max filter width (actual max ~43)

// ---------------- persistent table scratch ----------------
__device__ float2 g_w01[FPc];     // (w0, w1) per frequency bin
__device__ int    g_i0[FPc];      // first nonzero mel index per bin (<=126)
__device__ float  g_csr[CSRK*MM]; // k-major: g_csr[k*MM + m] = fb[lo[m]+k, m]
__device__ int    g_lo[MM];
__device__ int    g_cnt[MM];      // padded to multiple of 4, <= CSRK

// ---------------- prep: per-frequency 2-sparse table ----------------
__global__ void prep_f_kernel(const float* __restrict__ fb) {
    int f = blockIdx.x * blockDim.x + threadIdx.x;
    if (f >= FPc) return;
    if (f >= FF) { g_w01[f] = make_float2(0.f, 0.f); g_i0[f] = 0; return; }
    int fm = -1;
    for (int m = 0; m < MM; ++m) {
        if (fb[f * MM + m] > 0.f) { fm = m; break; }
    }
    if (fm < 0) { g_w01[f] = make_float2(0.f, 0.f); g_i0[f] = 0; return; }
    int i0 = fm > MM - 2 ? MM - 2 : fm;
    g_i0[f]  = i0;
    g_w01[f] = make_float2(fb[f * MM + i0], fb[f * MM + i0 + 1]);
}

// ---------------- prep: per-mel CSR (support range + weights) ----------------
__global__ void prep_m_kernel(const float* __restrict__ fb) {
    __shared__ int s_mn[128], s_mx[128];
    const int m = blockIdx.x;
    const int t = threadIdx.x;
    int mn = FF, mx = -1;
    for (int f = t; f < FF; f += 128) {
        if (fb[f * MM + m] > 0.f) { mn = min(mn, f); mx = max(mx, f); }
    }
    s_mn[t] = mn; s_mx[t] = mx;
    __syncthreads();
    for (int s = 64; s > 0; s >>= 1) {
        if (t < s) { s_mn[t] = min(s_mn[t], s_mn[t + s]); s_mx[t] = max(s_mx[t], s_mx[t + s]); }
        __syncthreads();
    }
    const int lo  = (s_mx[0] < 0) ? 0 : s_mn[0];
    int cnt = (s_mx[0] < 0) ? 0 : (s_mx[0] + 1 - lo);
    if (cnt > CSRK) cnt = CSRK;          // structurally impossible; safety clamp
    const int cntp = (cnt + 3) & ~3;
    if (t == 0) { g_lo[m] = lo; g_cnt[m] = cntp; }
    if (t < CSRK) {
        float w = (t < cnt) ? fb[(lo + t) * MM + m] : 0.f;
        g_csr[t * MM + m] = w;
    }
}

// ---------------- SMEM layout (floats) ----------------
#define OFF_SPEC 0
#define OFF_MEL  (OFF_SPEC + ROWS * SSTR)          // 35072
#define OFF_DIFF (OFF_MEL  + ROWS * DSTR)          // 39328
#define OFF_W01  (OFF_DIFF + ROWS * DSTR)          // 43584 (8B aligned)
#define OFF_CSR  (OFF_W01  + 2 * FPc)              // 45760
#define OFF_LO   (OFF_CSR  + CSRK * MM)            // 53952
#define OFF_CNT  (OFF_LO   + MM)                   // 54080
#define OFF_I0   (OFF_CNT  + MM)                   // 54208
#define SM_FLOATS (OFF_I0 + (FPc + 3) / 4)         // 54480 floats = 217920 B

// ---------------- main persistent kernel ----------------
__global__ __launch_bounds__(NTHR, 1)
void invmel_kernel(const float* __restrict__ melspec,
                   const float* __restrict__ spec_init,
                   float* __restrict__ out) {
    extern __shared__ float smem[];
    float*  s_spec = smem + OFF_SPEC;
    float*  s_mel  = smem + OFF_MEL;
    float*  s_diff = smem + OFF_DIFF;
    float2* s_w01  = reinterpret_cast<float2*>(smem + OFF_W01);
    float*  s_csr  = smem + OFF_CSR;
    int*    s_lo   = reinterpret_cast<int*>(smem + OFF_LO);
    int*    s_cnt  = reinterpret_cast<int*>(smem + OFF_CNT);
    unsigned char* s_i0 = reinterpret_cast<unsigned char*>(smem + OFF_I0);

    const int tid  = threadIdx.x;
    const int row0 = blockIdx.x * ROWS;   // base bt row
    const int b    = row0 / TT;
    const int t0   = row0 - b * TT;       // 32 consecutive t in same b

    // ---- load tables into SMEM ----
    for (int i = tid; i < FPc; i += NTHR) {
        s_w01[i] = g_w01[i];
        s_i0[i]  = (unsigned char)g_i0[i];
    }
    for (int i = tid; i < CSRK * MM; i += NTHR) s_csr[i] = g_csr[i];
    if (tid < MM) { s_lo[tid] = g_lo[tid]; s_cnt[tid] = g_cnt[tid]; }

    // ---- load spec (coalesced over f; pad [FF,FPc) with 0) ----
    for (int i = tid; i < ROWS * FPc; i += NTHR) {
        const int r = i / FPc;
        const int f = i - r * FPc;
        s_spec[r * SSTR + f] = (f < FF) ? spec_init[(size_t)(row0 + r) * FF + f] : 0.f;
    }
    // ---- load mel: s_mel[r][m] = melspec[b][m][t0+r]  (coalesced over t) ----
    for (int i = tid; i < ROWS * MM; i += NTHR) {
        const int m = i >> 5;
        const int r = i & 31;
        s_mel[r * DSTR + m] = melspec[((size_t)b * MM + m) * TT + t0 + r];
    }
    __syncthreads();

    // ---- role assignment ----
    const int row = tid >> 4;     // 0..31
    const int q   = tid & 15;     // 0..15
    const int f0  = q * CHNK;
    const int sbase = row * SSTR;
    const int dbase = row * DSTR;

    float buf[CHNK];
    #pragma unroll
    for (int j = 0; j < CHNK; ++j) buf[j] = 0.f;

    for (int it = 0; it < NITER; ++it) {
        // ======== phase A: diff[row][m] = mel - sum_k csr(m,k)*spec[lo+k] ========
        #pragma unroll
        for (int j = 0; j < 8; ++j) {
            const int m  = 16 * j + q;
            const int lo = s_lo[m];
            const int cn = s_cnt[m];
            const float* __restrict__ cw = s_csr + m;
            const float* __restrict__ sp = s_spec + sbase + lo;
            float acc = 0.f;
            for (int k = 0; k < cn; k += 4) {
                acc = fmaf(cw[(k + 0) * MM], sp[k + 0], acc);
                acc = fmaf(cw[(k + 1) * MM], sp[k + 1], acc);
                acc = fmaf(cw[(k + 2) * MM], sp[k + 2], acc);
                acc = fmaf(cw[(k + 3) * MM], sp[k + 3], acc);
            }
            s_diff[dbase + m] = s_mel[dbase + m] - acc;
        }
        __syncthreads();

        // ======== phase C: grad/momentum/update per f (buf in registers) ========
        #pragma unroll
        for (int j = 0; j < CHNK; ++j) {
            const int f = f0 + j;
            const float2 w = s_w01[f];
            const int   i0 = (int)s_i0[f];
            const float d0 = s_diff[dbase + i0];
            const float d1 = s_diff[dbase + i0 + 1];
            const float dot = fmaf(w.y, d1, w.x * d0);
            buf[j] = fmaf(-INVc, dot, MOMc * buf[j]);
            const float sp = fmaf(-LRc, buf[j], s_spec[sbase + f]);
            s_spec[sbase + f] = fmaxf(sp, 0.f);
        }
        __syncthreads();
    }

    // ---- epilogue: out[b][f][t0+r] = spec[r][f], 4-row float4 stores ----
    for (int f = tid; f < FF; f += NTHR) {
        float* __restrict__ op = out + ((size_t)b * FF + f) * TT + t0;
        const float* __restrict__ spp = s_spec + f;
        #pragma unroll
        for (int r = 0; r < ROWS; r += 4) {
            float4 v;
            v.x = spp[(r + 0) * SSTR];
            v.y = spp[(r + 1) * SSTR];
            v.z = spp[(r + 2) * SSTR];
            v.w = spp[(r + 3) * SSTR];
            *reinterpret_cast<float4*>(op + r) = v;
        }
    }
}

// ---------------- launch ----------------
extern "C" void kernel_launch(void* const* d_in, const int* in_sizes, int n_in,
                              void* d_out, int out_size) {
    const float* melspec   = (const float*)d_in[0];  // (4,128,1024)
    const float* spec_init = (const float*)d_in[1];  // (4,1024,1025)
    const float* fb        = (const float*)d_in[2];  // (1025,128)
    float* out             = (float*)d_out;          // (4,1025,1024)

    const int smem_bytes = SM_FLOATS * sizeof(float);   // 217920
    cudaFuncSetAttribute(invmel_kernel, cudaFuncAttributeMaxDynamicSharedMemorySize, smem_bytes);

    prep_f_kernel<<<(FPc + 127) / 128, 128>>>(fb);
    prep_m_kernel<<<MM, 128>>>(fb);
    invmel_kernel<<<NCTA, NTHR, smem_bytes>>>(melspec, spec_init, out);
}

// round 5
// speedup vs baseline: 18.5125x; 1.9754x over previous
#include <cuda_runtime.h>

// ---------------- problem constants ----------------
#define MM    128            // n_mels
#define FF    1025           // n_stft
#define FPc   1088           // padded F = 16*68
#define SSTR  1104           // spec SMEM row stride: 1104 % 32 == 16, % 4 == 0
#define DSTR  144            // mel/diff SMEM row stride: 144 % 32 == 16
#define TT    1024
#define NITER 20
#define LRc   0.3f
#define MOMc  0.9f
#define INVc  (2.0f / 4096.0f)

#define ROWS  32             // rows per CTA
#define NTHR  512
#define NCTA  128            // 4096 / 32 — single wave
#define CHNK  68             // f per thread lane-group (FPc/16)
#define NC4M  16             // max float4 chunks per mel (64 k slots)

// ---------------- persistent table scratch ----------------
__device__ float2 g_w01[FPc];        // (w0, w1) per frequency bin
__device__ int    g_i0[FPc];         // first mel index per bin (<=126)
__device__ float4 g_csr4[NC4M * MM]; // chunk-major: g_csr4[c*MM + m] = fb[lo_al+4c .. +3, m]
__device__ int    g_lo[MM];          // aligned lo (multiple of 4)
__device__ int    g_nc4[MM];         // number of float4 chunks (<=12)

// ---------------- merged prep kernel ----------------
// blocks [0,272): per-f 2-sparse table (4 warps = 4 f per block)
// blocks [272,400): per-mel aligned CSR
__global__ void prep_kernel(const float* __restrict__ fb) {
    const int blk = blockIdx.x;
    if (blk < 272) {
        const int warp = threadIdx.x >> 5;
        const int lane = threadIdx.x & 31;
        const int f = blk * 4 + warp;
        if (f >= FF) {
            if (f < FPc && lane == 0) { g_w01[f] = make_float2(0.f, 0.f); g_i0[f] = 0; }
            return;
        }
        const float* fr = fb + f * MM;
        unsigned b0 = __ballot_sync(0xffffffffu, fr[lane]      > 0.f);
        unsigned b1 = __ballot_sync(0xffffffffu, fr[lane + 32] > 0.f);
        unsigned b2 = __ballot_sync(0xffffffffu, fr[lane + 64] > 0.f);
        unsigned b3 = __ballot_sync(0xffffffffu, fr[lane + 96] > 0.f);
        if (lane == 0) {
            int fm = b0 ? (__ffs(b0) - 1)
                   : b1 ? (32 + __ffs(b1) - 1)
                   : b2 ? (64 + __ffs(b2) - 1)
                   : b3 ? (96 + __ffs(b3) - 1) : -1;
            if (fm < 0) { g_w01[f] = make_float2(0.f, 0.f); g_i0[f] = 0; }
            else {
                int i0 = fm > 126 ? 126 : fm;
                g_i0[f] = i0;
                g_w01[f] = make_float2(fr[i0], fr[i0 + 1]);
            }
        }
    } else {
        __shared__ int s_mn[128], s_mx[128];
        const int m = blk - 272;
        const int t = threadIdx.x;
        int mn = FF, mx = -1;
        for (int f = t; f < FF; f += 128) {
            if (fb[f * MM + m] > 0.f) { mn = min(mn, f); mx = max(mx, f); }
        }
        s_mn[t] = mn; s_mx[t] = mx;
        __syncthreads();
        for (int s = 64; s > 0; s >>= 1) {
            if (t < s) { s_mn[t] = min(s_mn[t], s_mn[t + s]); s_mx[t] = max(s_mx[t], s_mx[t + s]); }
            __syncthreads();
        }
        const int lo_al = (s_mx[0] < 0) ? 0 : (s_mn[0] & ~3);
        int cnt = (s_mx[0] < 0) ? 0 : (s_mx[0] + 1 - lo_al);
        int cnt_al = (cnt + 3) & ~3;
        if (cnt_al > 4 * NC4M) cnt_al = 4 * NC4M;   // structurally impossible; safety
        if (t == 0) { g_lo[m] = lo_al; g_nc4[m] = cnt_al >> 2; }
        if (t < 4 * NC4M) {
            // fb is zero outside the support, so unconditional reads are exact
            float w = (lo_al + t < FF) ? fb[(lo_al + t) * MM + m] : 0.f;
            reinterpret_cast<float*>(g_csr4)[((t >> 2) * MM + m) * 4 + (t & 3)] = w;
        }
    }
}

// ---------------- SMEM layout (floats) ----------------
#define OFF_SPEC 0
#define OFF_MEL  (OFF_SPEC + ROWS * SSTR)          // 35328
#define OFF_DIFF (OFF_MEL  + ROWS * DSTR)          // 39936
#define OFF_W01  (OFF_DIFF + ROWS * DSTR)          // 44544 (8B aligned)
#define OFF_CSR  (OFF_W01  + 2 * FPc)              // 46720 (16B aligned)
#define OFF_LO   (OFF_CSR  + 4 * NC4M * MM)        // 54912
#define OFF_NC   (OFF_LO   + MM)                   // 55040
#define OFF_I0   (OFF_NC   + MM)                   // 55168
#define SM_FLOATS (OFF_I0 + FPc / 4)               // 55440 floats = 221760 B

// ---------------- main persistent kernel ----------------
__global__ __launch_bounds__(NTHR, 1)
void invmel_kernel(const float* __restrict__ melspec,
                   const float* __restrict__ spec_init,
                   float* __restrict__ out) {
    extern __shared__ float smem[];
    float*  s_spec = smem + OFF_SPEC;
    float*  s_mel  = smem + OFF_MEL;
    float*  s_diff = smem + OFF_DIFF;
    float2* s_w01  = reinterpret_cast<float2*>(smem + OFF_W01);
    float4* s_csr4 = reinterpret_cast<float4*>(smem + OFF_CSR);
    int*    s_lo   = reinterpret_cast<int*>(smem + OFF_LO);
    int*    s_nc   = reinterpret_cast<int*>(smem + OFF_NC);
    unsigned char* s_i0 = reinterpret_cast<unsigned char*>(smem + OFF_I0);

    const int tid  = threadIdx.x;
    const int row0 = blockIdx.x * ROWS;   // base bt row
    const int b    = row0 / TT;
    const int t0   = row0 - b * TT;

    // ---- tables into SMEM ----
    for (int i = tid; i < FPc; i += NTHR) {
        s_w01[i] = g_w01[i];
        s_i0[i]  = (unsigned char)g_i0[i];
    }
    {
        const float4* g4 = g_csr4;
        for (int i = tid; i < NC4M * MM; i += NTHR) s_csr4[i] = g4[i];
    }
    if (tid < MM) { s_lo[tid] = g_lo[tid]; s_nc[tid] = g_nc4[tid]; }

    // ---- spec tile (coalesced over f; pad [FF,FPc) with 0) ----
    for (int i = tid; i < ROWS * FPc; i += NTHR) {
        const int r = i / FPc;
        const int f = i - r * FPc;
        s_spec[r * SSTR + f] = (f < FF) ? spec_init[(size_t)(row0 + r) * FF + f] : 0.f;
    }
    // ---- mel tile: s_mel[r][m] = melspec[b][m][t0+r] (coalesced over t) ----
    for (int i = tid; i < ROWS * MM; i += NTHR) {
        const int m = i >> 5;
        const int r = i & 31;
        s_mel[r * DSTR + m] = melspec[((size_t)b * MM + m) * TT + t0 + r];
    }
    __syncthreads();

    // ---- roles ----
    const int row   = tid >> 4;   // 0..31
    const int q     = tid & 15;   // 0..15
    const int sbase = row * SSTR;
    const int dbase = row * DSTR;

    // hoisted per-mel metadata (iteration-invariant)
    int lo8[8], nc8[8];
    #pragma unroll
    for (int j = 0; j < 8; ++j) {
        const int m = 16 * j + q;
        lo8[j] = s_lo[m];
        nc8[j] = s_nc[m];
    }

    float buf[CHNK];
    #pragma unroll
    for (int j = 0; j < CHNK; ++j) buf[j] = 0.f;

    for (int it = 0; it < NITER; ++it) {
        // ======== phase A: diff[row][m] = mel[m] - sum_k w(m,k)*spec[lo_al+k] ========
        #pragma unroll
        for (int j = 0; j < 8; ++j) {
            const int m = 16 * j + q;
            const float4* __restrict__ cw  = s_csr4 + m;
            const float4* __restrict__ sp4 = reinterpret_cast<const float4*>(s_spec + sbase + lo8[j]);
            float a0 = 0.f, a1 = 0.f;
            const int n = nc8[j];
            #pragma unroll 2
            for (int c = 0; c < n; ++c) {
                const float4 w = cw[c * MM];
                const float4 s = sp4[c];
                a0 = fmaf(w.x, s.x, a0);
                a1 = fmaf(w.y, s.y, a1);
                a0 = fmaf(w.z, s.z, a0);
                a1 = fmaf(w.w, s.w, a1);
            }
            s_diff[dbase + m] = s_mel[dbase + m] - (a0 + a1);
        }
        __syncthreads();

        // ======== phase C: grad / momentum / clamp per f (interleaved f = 16j+q) ========
        #pragma unroll
        for (int j = 0; j < CHNK; ++j) {
            const int f = 16 * j + q;
            const float2 w = s_w01[f];
            const int   i0 = (int)s_i0[f];
            const float d0 = s_diff[dbase + i0];
            const float d1 = s_diff[dbase + i0 + 1];
            const float dot = fmaf(w.y, d1, w.x * d0);
            const float bv  = fmaf(MOMc, buf[j], -INVc * dot);
            buf[j] = bv;
            const float sp = fmaf(-LRc, bv, s_spec[sbase + f]);
            s_spec[sbase + f] = fmaxf(sp, 0.f);
        }
        __syncthreads();
    }

    // ---- epilogue: out[b][f][t0+r] = spec[r][f] ----
    for (int f = tid; f < FF; f += NTHR) {
        float* __restrict__ op = out + ((size_t)b * FF + f) * TT + t0;
        const float* __restrict__ spp = s_spec + f;
        #pragma unroll
        for (int r = 0; r < ROWS; r += 4) {
            float4 v;
            v.x = spp[(r + 0) * SSTR];
            v.y = spp[(r + 1) * SSTR];
            v.z = spp[(r + 2) * SSTR];
            v.w = spp[(r + 3) * SSTR];
            *reinterpret_cast<float4*>(op + r) = v;
        }
    }
}

// ---------------- launch ----------------
extern "C" void kernel_launch(void* const* d_in, const int* in_sizes, int n_in,
                              void* d_out, int out_size) {
    const float* melspec   = (const float*)d_in[0];  // (4,128,1024)
    const float* spec_init = (const float*)d_in[1];  // (4,1024,1025)
    const float* fb        = (const float*)d_in[2];  // (1025,128)
    float* out             = (float*)d_out;          // (4,1025,1024)

    const int smem_bytes = SM_FLOATS * sizeof(float);   // 221760
    cudaFuncSetAttribute(invmel_kernel, cudaFuncAttributeMaxDynamicSharedMemorySize, smem_bytes);

    prep_kernel<<<400, 128>>>(fb);
    invmel_kernel<<<NCTA, NTHR, smem_bytes>>>(melspec, spec_init, out);
}

// round 6
// speedup vs baseline: 21.8031x; 1.1778x over previous
#include <cuda_runtime.h>

// ---------------- problem constants ----------------
#define MM    128            // n_mels
#define FF    1025           // n_stft
#define FPc   1088           // padded F
#define SSTR  1104           // spec SMEM row stride: %32==16, %4==0
#define DSTR  144            // mel/diff SMEM row stride: %32==16
#define TT    1024
#define NITER 20
#define LRc   0.3f
#define MOMc  0.9f
#define INVc  (2.0f / 4096.0f)

#define ROWS  28             // rows per CTA (max)
#define NTHR  512
#define NCTA  147            // 146*28 + 8 = 4096, single wave on 148 SMs
#define NJ    34             // phase C steps: 34 * 32 f = 1088
#define NC4M  12             // float4 chunks per mel (48 k slots >= max width ~46)

// ---------------- persistent table scratch ----------------
__device__ float   g_w0[FPc];         // w0 per bin (w1 = 1-w0 via identity)
__device__ uchar2  g_i01[FPc];        // (i0, i1) diff indices; 128 = zero pad slot
__device__ float4  g_csr4[NC4M*MM];   // chunk-major: g_csr4[c*MM+m] = fb[lo+4c..+3, m]
__device__ int     g_lo[MM];          // aligned lo (multiple of 4)
__device__ int     g_nc4[MM];         // chunks per mel (<= NC4M)

// ---------------- merged prep kernel ----------------
// blocks [0,272): per-f table (4 warps = 4 f per block)
// blocks [272,400): per-mel aligned CSR
__global__ void prep_kernel(const float* __restrict__ fb) {
    const int blk = blockIdx.x;
    if (blk < 272) {
        const int warp = threadIdx.x >> 5;
        const int lane = threadIdx.x & 31;
        const int f = blk * 4 + warp;
        if (f >= FF) {
            if (f < FPc && lane == 0) {
                g_w0[f] = 0.f; g_i01[f] = make_uchar2(128, 128);
            }
            return;
        }
        const float* fr = fb + f * MM;
        unsigned b0 = __ballot_sync(0xffffffffu, fr[lane]      > 0.f);
        unsigned b1 = __ballot_sync(0xffffffffu, fr[lane + 32] > 0.f);
        unsigned b2 = __ballot_sync(0xffffffffu, fr[lane + 64] > 0.f);
        unsigned b3 = __ballot_sync(0xffffffffu, fr[lane + 96] > 0.f);
        if (lane == 0) {
            int fm = b0 ? (__ffs(b0) - 1)
                   : b1 ? (32 + __ffs(b1) - 1)
                   : b2 ? (64 + __ffs(b2) - 1)
                   : b3 ? (96 + __ffs(b3) - 1) : -1;
            if (fm < 0) {
                g_w0[f] = 0.f; g_i01[f] = make_uchar2(128, 128);
            } else {
                float w0 = fr[fm];
                int i1 = (fm < 127 && fr[fm + 1] > 0.f) ? fm + 1 : 128;
                g_w0[f] = w0;
                g_i01[f] = make_uchar2((unsigned char)fm, (unsigned char)i1);
            }
        }
    } else {
        __shared__ int s_mn[128], s_mx[128];
        const int m = blk - 272;
        const int t = threadIdx.x;
        int mn = FF, mx = -1;
        for (int f = t; f < FF; f += 128) {
            if (fb[f * MM + m] > 0.f) { mn = min(mn, f); mx = max(mx, f); }
        }
        s_mn[t] = mn; s_mx[t] = mx;
        __syncthreads();
        for (int s = 64; s > 0; s >>= 1) {
            if (t < s) { s_mn[t] = min(s_mn[t], s_mn[t + s]); s_mx[t] = max(s_mx[t], s_mx[t + s]); }
            __syncthreads();
        }
        const int lo_al = (s_mx[0] < 0) ? 0 : (s_mn[0] & ~3);
        int cnt = (s_mx[0] < 0) ? 0 : (s_mx[0] + 1 - lo_al);
        int cnt_al = (cnt + 3) & ~3;
        if (cnt_al > 4 * NC4M) cnt_al = 4 * NC4M;   // structurally impossible; safety
        if (t == 0) { g_lo[m] = lo_al; g_nc4[m] = cnt_al >> 2; }
        if (t < 4 * NC4M) {
            // fb is zero outside [mn,mx], so unconditional reads are exact
            float w = (lo_al + t < FF) ? fb[(lo_al + t) * MM + m] : 0.f;
            reinterpret_cast<float*>(g_csr4)[((t >> 2) * MM + m) * 4 + (t & 3)] = w;
        }
    }
}

// ---------------- SMEM layout (floats) ----------------
#define OFF_SPEC 0
#define OFF_MEL  (OFF_SPEC + ROWS * SSTR)          // 30912
#define OFF_DIFF (OFF_MEL  + ROWS * DSTR)          // 34944
#define OFF_W0   (OFF_DIFF + ROWS * DSTR)          // 38976
#define OFF_CSR  (OFF_W0   + FPc)                  // 40064 (16B aligned)
#define OFF_LO   (OFF_CSR  + 4 * NC4M * MM)        // 46208
#define OFF_NC   (OFF_LO   + MM)                   // 46336
#define OFF_I01  (OFF_NC   + MM)                   // 46464
#define SM_FLOATS (OFF_I01 + (2 * FPc) / 4)        // 47008 floats = 188032 B

// ---------------- main persistent kernel ----------------
__global__ __launch_bounds__(NTHR, 1)
void invmel_kernel(const float* __restrict__ melspec,
                   const float* __restrict__ spec_init,
                   float* __restrict__ out) {
    extern __shared__ float smem[];
    float*  s_spec = smem + OFF_SPEC;
    float*  s_mel  = smem + OFF_MEL;
    float*  s_diff = smem + OFF_DIFF;
    float*  s_w0   = smem + OFF_W0;
    float4* s_csr4 = reinterpret_cast<float4*>(smem + OFF_CSR);
    int*    s_lo   = reinterpret_cast<int*>(smem + OFF_LO);
    int*    s_nc   = reinterpret_cast<int*>(smem + OFF_NC);
    unsigned short* s_i01 = reinterpret_cast<unsigned short*>(smem + OFF_I01);

    const int tid   = threadIdx.x;
    const int row0  = blockIdx.x * ROWS;
    const int nrows = min(ROWS, 4096 - row0);     // 28, or 8 for last CTA

    // ---- tables ----
    for (int i = tid; i < FPc; i += NTHR) {
        s_w0[i]  = g_w0[i];
        s_i01[i] = reinterpret_cast<const unsigned short*>(g_i01)[i];
    }
    for (int i = tid; i < NC4M * MM; i += NTHR) s_csr4[i] = g_csr4[i];
    if (tid < MM) { s_lo[tid] = g_lo[tid]; s_nc[tid] = g_nc4[tid]; }

    // ---- zero diff (incl. pad slot m=128 used by the i1 trick) ----
    for (int i = tid; i < ROWS * DSTR; i += NTHR) s_diff[i] = 0.f;

    // ---- spec tile (coalesced over f; pad [FF,FPc) with 0) ----
    for (int i = tid; i < nrows * FPc; i += NTHR) {
        const int r = i / FPc;
        const int f = i - r * FPc;
        s_spec[r * SSTR + f] = (f < FF) ? spec_init[(size_t)(row0 + r) * FF + f] : 0.f;
    }
    // ---- mel tile: s_mel[r][m] = melspec[b_r][m][t_r] (r fastest for coalescing) ----
    for (int i = tid; i < nrows * MM; i += NTHR) {
        const int m = i / nrows;
        const int r = i - m * nrows;
        const int g = row0 + r;
        const int b = g >> 10;
        const int t = g & 1023;
        s_mel[r * DSTR + m] = melspec[((size_t)b * MM + m) * TT + t];
    }
    __syncthreads();

    // ---- roles ----
    const int row    = tid >> 4;   // 0..31
    const int q      = tid & 15;   // 0..15
    const int sbase  = row * SSTR;
    const int dbase  = row * DSTR;
    const bool active = (row < nrows);

    // hoisted per-mel metadata (iteration-invariant)
    int lo8[8], nc8[8];
    #pragma unroll
    for (int j = 0; j < 8; ++j) {
        const int m = 16 * j + q;
        lo8[j] = s_lo[m];
        nc8[j] = s_nc[m];
    }

    float2 buf[NJ];
    #pragma unroll
    for (int j = 0; j < NJ; ++j) buf[j] = make_float2(0.f, 0.f);

    for (int it = 0; it < NITER; ++it) {
        // ======== phase A: diff[row][m] = mel[m] - sum_k w(m,k)*spec[lo+k] ========
        if (active) {
            #pragma unroll
            for (int j = 0; j < 8; ++j) {
                const int m = 16 * j + q;
                const float4* __restrict__ cw  = s_csr4 + m;
                const float4* __restrict__ sp4 = reinterpret_cast<const float4*>(s_spec + sbase + lo8[j]);
                float a0 = 0.f, a1 = 0.f;
                const int n = nc8[j];
                #pragma unroll 2
                for (int c = 0; c < n; ++c) {
                    const float4 w = cw[c * MM];
                    const float4 s = sp4[c];
                    a0 = fmaf(w.x, s.x, a0);
                    a1 = fmaf(w.y, s.y, a1);
                    a0 = fmaf(w.z, s.z, a0);
                    a1 = fmaf(w.w, s.w, a1);
                }
                s_diff[dbase + m] = s_mel[dbase + m] - (a0 + a1);
            }
        }
        __syncthreads();

        // ======== phase C: float2 over f-pairs; dot = d1 + w0*(d0-d1) ========
        if (active) {
            #pragma unroll
            for (int j = 0; j < NJ; ++j) {
                const int f = 32 * j + 2 * q;
                const float2 w = *reinterpret_cast<const float2*>(s_w0 + f);
                const uchar4 ii = *reinterpret_cast<const uchar4*>(s_i01 + f);
                const float d0a = s_diff[dbase + ii.x];
                const float d1a = s_diff[dbase + ii.y];
                const float d0b = s_diff[dbase + ii.z];
                const float d1b = s_diff[dbase + ii.w];
                const float dota = fmaf(w.x, d0a - d1a, d1a);
                const float dotb = fmaf(w.y, d0b - d1b, d1b);
                float2 bv;
                bv.x = fmaf(MOMc, buf[j].x, -INVc * dota);
                bv.y = fmaf(MOMc, buf[j].y, -INVc * dotb);
                buf[j] = bv;
                float2 sp = *reinterpret_cast<const float2*>(s_spec + sbase + f);
                sp.x = fmaxf(fmaf(-LRc, bv.x, sp.x), 0.f);
                sp.y = fmaxf(fmaf(-LRc, bv.y, sp.y), 0.f);
                *reinterpret_cast<float2*>(s_spec + sbase + f) = sp;
            }
        }
        __syncthreads();
    }

    // ---- epilogue: out[b][f][t] = spec[r][f]; 4-row float4 groups (batch-pure) ----
    for (int f = tid; f < FF; f += NTHR) {
        const float* __restrict__ spp = s_spec + f;
        #pragma unroll 2
        for (int r = 0; r < nrows; r += 4) {
            const int g = row0 + r;           // multiple of 4; group shares batch
            const int b = g >> 10;
            const int t = g & 1023;
            float4 v;
            v.x = spp[(r + 0) * SSTR];
            v.y = spp[(r + 1) * SSTR];
            v.z = spp[(r + 2) * SSTR];
            v.w = spp[(r + 3) * SSTR];
            *reinterpret_cast<float4*>(out + ((size_t)b * FF + f) * TT + t) = v;
        }
    }
}

// ---------------- launch ----------------
extern "C" void kernel_launch(void* const* d_in, const int* in_sizes, int n_in,
                              void* d_out, int out_size) {
    const float* melspec   = (const float*)d_in[0];  // (4,128,1024)
    const float* spec_init = (const float*)d_in[1];  // (4,1024,1025)
    const float* fb        = (const float*)d_in[2];  // (1025,128)
    float* out             = (float*)d_out;          // (4,1025,1024)

    const int smem_bytes = SM_FLOATS * sizeof(float);   // 188032
    cudaFuncSetAttribute(invmel_kernel, cudaFuncAttributeMaxDynamicSharedMemorySize, smem_bytes);

    prep_kernel<<<400, 128>>>(fb);
    invmel_kernel<<<NCTA, NTHR, smem_bytes>>>(melspec, spec_init, out);
}